// round 2
// baseline (speedup 1.0000x reference)
#include <cuda_runtime.h>
#include <cuda_bf16.h>
#include <cstdint>

// Problem constants
#define BB 4
#define NN 4096
#define DIMD 1024
#define HH 16
#define DHD 64
#define MROWS (BB * NN)          // 16384
#define QKVN (3 * DIMD)          // 3072

// ---------------- scratch (device globals; no runtime allocation) -------------
__device__ float gQ[(size_t)MROWS * DIMD];   // [m][h*64+d]  elu(q)+1
__device__ float gK[(size_t)MROWS * DIMD];   // masked, elu+1
__device__ float gV[(size_t)MROWS * DIMD];   // masked
__device__ float gS[(size_t)MROWS * DIMD];   // scaled attention output (pre-Wout)
__device__ float gKV[(size_t)BB * HH * DHD * DHD];  // [bh][d][e]
__device__ float gKsum[(size_t)BB * HH * DHD];      // [bh][d]

__device__ __forceinline__ float elu1(float x) {
    return x > 0.0f ? x + 1.0f : __expf(x);
}

// ---------------- K1: qkv GEMM  C = x @ Wqkv, fused epilogue ------------------
// 128x128 tile, BK=8, 256 threads, 8x8 per thread.
__global__ __launch_bounds__(256) void gemm_qkv_kernel(
    const float* __restrict__ A,            // [MROWS, DIMD]
    const float* __restrict__ Bm,           // [DIMD, QKVN]
    const int* __restrict__ mask)           // [MROWS] (bool stored as int32)
{
    __shared__ float As[8][128];
    __shared__ float Bs[8][128];

    const int tid = threadIdx.x;
    const int bm = blockIdx.y;
    const int bn = blockIdx.x;

    const int arow = tid >> 1;
    const int acol = (tid & 1) * 4;
    const int brow = tid >> 5;
    const int bcol = (tid & 31) * 4;

    const float* Aptr = A + (size_t)(bm * 128 + arow) * DIMD + acol;
    const float* Bptr = Bm + (size_t)brow * QKVN + bn * 128 + bcol;

    const int ty = tid >> 4;
    const int tx = tid & 15;

    float acc[8][8];
    #pragma unroll
    for (int i = 0; i < 8; i++)
        #pragma unroll
        for (int j = 0; j < 8; j++) acc[i][j] = 0.0f;

    for (int k0 = 0; k0 < DIMD; k0 += 8) {
        float4 a4 = *(const float4*)(Aptr + k0);
        float4 b4 = *(const float4*)(Bptr + (size_t)k0 * QKVN);
        As[acol + 0][arow] = a4.x;
        As[acol + 1][arow] = a4.y;
        As[acol + 2][arow] = a4.z;
        As[acol + 3][arow] = a4.w;
        *(float4*)&Bs[brow][bcol] = b4;
        __syncthreads();

        #pragma unroll
        for (int kk = 0; kk < 8; kk++) {
            float a[8], b[8];
            #pragma unroll
            for (int i = 0; i < 8; i++) a[i] = As[kk][ty * 8 + i];
            #pragma unroll
            for (int j = 0; j < 8; j++) b[j] = Bs[kk][tx * 8 + j];
            #pragma unroll
            for (int i = 0; i < 8; i++)
                #pragma unroll
                for (int j = 0; j < 8; j++) acc[i][j] += a[i] * b[j];
        }
        __syncthreads();
    }

    const int row0 = bm * 128 + ty * 8;
    const int col0 = bn * 128 + tx * 8;

    #pragma unroll
    for (int i = 0; i < 8; i++) {
        const int m = row0 + i;
        const float mk = (mask[m] != 0) ? 1.0f : 0.0f;
        #pragma unroll
        for (int j = 0; j < 8; j++) {
            const int c = col0 + j;
            const float v = acc[i][j];
            if (c < DIMD) {
                gQ[(size_t)m * DIMD + c] = elu1(v);
            } else if (c < 2 * DIMD) {
                gK[(size_t)m * DIMD + (c - DIMD)] = mk * elu1(v);
            } else {
                gV[(size_t)m * DIMD + (c - 2 * DIMD)] = mk * v;
            }
        }
    }
}

// ---------------- K2: kv[bh][d][e] = sum_n k[n][d]*v[n][e]; ksum --------------
__global__ __launch_bounds__(256) void kv_reduce_kernel() {
    const int bh = blockIdx.x;               // 0..63
    const int b = bh / HH;
    const int h = bh % HH;
    const int tid = threadIdx.x;

    __shared__ float sk[8][64];
    __shared__ float sv[8][64];

    const int d = tid >> 2;                  // 0..63
    const int esub = (tid & 3) * 16;         // 0,16,32,48

    float acc[16];
    #pragma unroll
    for (int j = 0; j < 16; j++) acc[j] = 0.0f;
    float ksacc = 0.0f;

    const size_t rowbase = (size_t)b * NN;

    for (int n0 = 0; n0 < NN; n0 += 8) {
        #pragma unroll
        for (int r = 0; r < 4; r++) {
            const int idx = r * 256 + tid;   // 0..1023
            const int i = idx >> 7;          // 0..7
            const int col = idx & 127;
            const size_t off = (rowbase + n0 + i) * DIMD + h * DHD;
            if (col < 64) sk[i][col] = gK[off + col];
            else          sv[i][col - 64] = gV[off + (col - 64)];
        }
        __syncthreads();

        #pragma unroll
        for (int i = 0; i < 8; i++) {
            const float kd = sk[i][d];
            #pragma unroll
            for (int j = 0; j < 16; j++) acc[j] += kd * sv[i][esub + j];
        }
        if (tid < 64) {
            #pragma unroll
            for (int i = 0; i < 8; i++) ksacc += sk[i][tid];
        }
        __syncthreads();
    }

    const size_t kvbase = ((size_t)bh * 64 + d) * 64 + esub;
    #pragma unroll
    for (int j = 0; j < 16; j++) gKV[kvbase + j] = acc[j];
    if (tid < 64) gKsum[(size_t)bh * 64 + tid] = ksacc;
}

// ---------------- K3: out = (q @ kv) / (q . ksum + 1e-6) ----------------------
__global__ __launch_bounds__(256) void apply_kernel() {
    const int bh = blockIdx.x;               // 0..63
    const int chunk = blockIdx.y;            // 0..63 (64 n's each)
    const int b = bh / HH;
    const int h = bh % HH;
    const int tid = threadIdx.x;

    __shared__ float skv[64][64];
    __shared__ float sks[64];
    __shared__ float sq[4][64];

    {
        const size_t base = (size_t)bh * 4096;
        #pragma unroll
        for (int r = 0; r < 16; r++) {
            const int idx = r * 256 + tid;
            ((float*)skv)[idx] = gKV[base + idx];
        }
        if (tid < 64) sks[tid] = gKsum[(size_t)bh * 64 + tid];
    }
    __syncthreads();

    const int g = tid >> 6;                  // 0..3
    const int e = tid & 63;

    for (int it = 0; it < 16; it++) {
        const int n = chunk * 64 + it * 4 + g;
        const size_t off = ((size_t)b * NN + n) * DIMD + h * DHD;
        sq[g][e] = gQ[off + e];
        __syncthreads();

        float acc = 0.0f, qd = 0.0f;
        #pragma unroll
        for (int d = 0; d < 64; d++) {
            const float qv = sq[g][d];
            acc += qv * skv[d][e];
            qd += qv * sks[d];
        }
        gS[off + e] = acc / (qd + 1e-6f);
        __syncthreads();
    }
}

// ---------------- K4: out = gS @ Wout + bout ----------------------------------
__global__ __launch_bounds__(256) void gemm_out_kernel(
    const float* __restrict__ Bm,            // Wout [DIMD, DIMD]
    const float* __restrict__ bout,          // [DIMD]
    float* __restrict__ Out)                 // [MROWS, DIMD]
{
    __shared__ float As[8][128];
    __shared__ float Bs[8][128];

    const int tid = threadIdx.x;
    const int bm = blockIdx.y;
    const int bn = blockIdx.x;

    const int arow = tid >> 1;
    const int acol = (tid & 1) * 4;
    const int brow = tid >> 5;
    const int bcol = (tid & 31) * 4;

    const float* Aptr = gS + (size_t)(bm * 128 + arow) * DIMD + acol;
    const float* Bptr = Bm + (size_t)brow * DIMD + bn * 128 + bcol;

    const int ty = tid >> 4;
    const int tx = tid & 15;

    float acc[8][8];
    #pragma unroll
    for (int i = 0; i < 8; i++)
        #pragma unroll
        for (int j = 0; j < 8; j++) acc[i][j] = 0.0f;

    for (int k0 = 0; k0 < DIMD; k0 += 8) {
        float4 a4 = *(const float4*)(Aptr + k0);
        float4 b4 = *(const float4*)(Bptr + (size_t)k0 * DIMD);
        As[acol + 0][arow] = a4.x;
        As[acol + 1][arow] = a4.y;
        As[acol + 2][arow] = a4.z;
        As[acol + 3][arow] = a4.w;
        *(float4*)&Bs[brow][bcol] = b4;
        __syncthreads();

        #pragma unroll
        for (int kk = 0; kk < 8; kk++) {
            float a[8], b[8];
            #pragma unroll
            for (int i = 0; i < 8; i++) a[i] = As[kk][ty * 8 + i];
            #pragma unroll
            for (int j = 0; j < 8; j++) b[j] = Bs[kk][tx * 8 + j];
            #pragma unroll
            for (int i = 0; i < 8; i++)
                #pragma unroll
                for (int j = 0; j < 8; j++) acc[i][j] += a[i] * b[j];
        }
        __syncthreads();
    }

    const int row0 = bm * 128 + ty * 8;
    const int col0 = bn * 128 + tx * 8;

    #pragma unroll
    for (int i = 0; i < 8; i++) {
        const size_t m = row0 + i;
        #pragma unroll
        for (int j = 0; j < 8; j++) {
            const int c = col0 + j;
            Out[m * DIMD + c] = acc[i][j] + bout[c];
        }
    }
}

// ---------------- launcher ----------------------------------------------------
extern "C" void kernel_launch(void* const* d_in, const int* in_sizes, int n_in,
                              void* d_out, int out_size) {
    const float* x = (const float*)d_in[0];
    const int* mask = (const int*)d_in[1];
    const float* Wqkv = (const float*)d_in[2];
    const float* Wout = (const float*)d_in[3];
    const float* bout = (const float*)d_in[4];
    float* out = (float*)d_out;

    {
        dim3 grid(QKVN / 128, MROWS / 128);   // 24 x 128
        gemm_qkv_kernel<<<grid, 256>>>(x, Wqkv, mask);
    }
    {
        kv_reduce_kernel<<<BB * HH, 256>>>();
    }
    {
        dim3 grid(BB * HH, NN / 64);          // 64 x 64
        apply_kernel<<<grid, 256>>>();
    }
    {
        dim3 grid(DIMD / 128, MROWS / 128);   // 8 x 128
        gemm_out_kernel<<<grid, 256>>>(Wout, bout, out);
    }
}

// round 4
// speedup vs baseline: 2.3917x; 2.3917x over previous
#include <cuda_runtime.h>
#include <cuda_bf16.h>
#include <cstdint>

// Problem constants
#define BB 4
#define NN 4096
#define DIMD 1024
#define HH 16
#define DHD 64
#define MROWS (BB * NN)          // 16384
#define QKVN (3 * DIMD)          // 3072

#define BM 128
#define BN 128
#define BKK 16
#define PAD 4
#define NCHUNK 8

// ---------------- scratch (device globals; no runtime allocation) -------------
__device__ float gQ[(size_t)MROWS * DIMD];
__device__ float gK[(size_t)MROWS * DIMD];
__device__ float gV[(size_t)MROWS * DIMD];
__device__ float gS[(size_t)MROWS * DIMD];
__device__ float gKV[(size_t)BB * HH * DHD * DHD];
__device__ float gKsum[(size_t)BB * HH * DHD];
__device__ float gKVp[NCHUNK][BB * HH][DHD * DHD];
__device__ float gKsump[NCHUNK][BB * HH][DHD];

__device__ __forceinline__ float elu1(float x) {
    return x > 0.0f ? x + 1.0f : __expf(x);
}

// cvt.rna.tf32.f32 requires a b32 destination register.
__device__ __forceinline__ float to_tf32(float x) {
    uint32_t r;
    asm("cvt.rna.tf32.f32 %0, %1;" : "=r"(r) : "f"(x));
    return __uint_as_float(r);
}

__device__ __forceinline__ void mma_tf32(float c[4],
                                         uint32_t a0, uint32_t a1, uint32_t a2, uint32_t a3,
                                         uint32_t b0, uint32_t b1) {
    asm volatile(
        "mma.sync.aligned.m16n8k8.row.col.f32.tf32.tf32.f32 "
        "{%0,%1,%2,%3}, {%4,%5,%6,%7}, {%8,%9}, {%0,%1,%2,%3};"
        : "+f"(c[0]), "+f"(c[1]), "+f"(c[2]), "+f"(c[3])
        : "r"(a0), "r"(a1), "r"(a2), "r"(a3), "r"(b0), "r"(b1));
}

// ---------------- shared GEMM mainloop (TF32 mma) -----------------------------
// Block: 256 threads. Tile BM x BN, K-step BKK=16.
// Warp (wm,wn) owns 32x64: 2 m-atoms x 8 n-atoms of m16n8k8.
__device__ __forceinline__ void gemm_mainloop_tf32(
    const float* __restrict__ Aptr,   // &A[bm*128][0], row stride lda
    int lda,
    const float* __restrict__ Bptr,   // &B[0][bn*128], row stride ldb
    int ldb,
    int K,
    float (*As)[BM + PAD],            // [BKK][BM+PAD]
    float (*Bs)[BN + PAD],            // [BKK][BN+PAD]
    float acc[2][8][4])
{
    const int tid = threadIdx.x;
    const int lane = tid & 31;
    const int warp = tid >> 5;
    const int wm = warp & 3;
    const int wn = warp >> 2;
    const int g = lane >> 2;
    const int tig = lane & 3;

    // global load mapping
    const int a_row = tid >> 2;       // 0..63, +64 second pass
    const int a_c4 = tid & 3;         // k float4 index
    const int b_row = tid >> 5;       // 0..7, +8 second pass
    const int b_c4 = tid & 31;        // n float4 index

    float4 aR[2], bR[2];

    auto gload = [&](int k0) {
        #pragma unroll
        for (int p = 0; p < 2; p++) {
            aR[p] = *(const float4*)(Aptr + (size_t)(a_row + 64 * p) * lda + k0 + a_c4 * 4);
            bR[p] = *(const float4*)(Bptr + (size_t)(k0 + b_row + 8 * p) * ldb + b_c4 * 4);
        }
    };
    auto sstore = [&]() {
        #pragma unroll
        for (int p = 0; p < 2; p++) {
            As[a_c4 * 4 + 0][a_row + 64 * p] = to_tf32(aR[p].x);
            As[a_c4 * 4 + 1][a_row + 64 * p] = to_tf32(aR[p].y);
            As[a_c4 * 4 + 2][a_row + 64 * p] = to_tf32(aR[p].z);
            As[a_c4 * 4 + 3][a_row + 64 * p] = to_tf32(aR[p].w);
            float4 t;
            t.x = to_tf32(bR[p].x); t.y = to_tf32(bR[p].y);
            t.z = to_tf32(bR[p].z); t.w = to_tf32(bR[p].w);
            *(float4*)&Bs[b_row + 8 * p][b_c4 * 4] = t;
        }
    };
    auto compute = [&]() {
        #pragma unroll
        for (int kk = 0; kk < BKK; kk += 8) {
            uint32_t af[2][4];
            #pragma unroll
            for (int im = 0; im < 2; im++) {
                const int r0 = wm * 32 + im * 16;
                af[im][0] = __float_as_uint(As[kk + tig][r0 + g]);
                af[im][1] = __float_as_uint(As[kk + tig][r0 + g + 8]);
                af[im][2] = __float_as_uint(As[kk + tig + 4][r0 + g]);
                af[im][3] = __float_as_uint(As[kk + tig + 4][r0 + g + 8]);
            }
            uint32_t bf[8][2];
            #pragma unroll
            for (int in = 0; in < 8; in++) {
                const int c0 = wn * 64 + in * 8 + g;
                bf[in][0] = __float_as_uint(Bs[kk + tig][c0]);
                bf[in][1] = __float_as_uint(Bs[kk + tig + 4][c0]);
            }
            #pragma unroll
            for (int im = 0; im < 2; im++)
                #pragma unroll
                for (int in = 0; in < 8; in++)
                    mma_tf32(acc[im][in],
                             af[im][0], af[im][1], af[im][2], af[im][3],
                             bf[in][0], bf[in][1]);
        }
    };

    #pragma unroll
    for (int im = 0; im < 2; im++)
        #pragma unroll
        for (int in = 0; in < 8; in++)
            #pragma unroll
            for (int j = 0; j < 4; j++) acc[im][in][j] = 0.0f;

    gload(0);
    sstore();
    __syncthreads();
    for (int k0 = BKK; k0 < K; k0 += BKK) {
        gload(k0);
        compute();
        __syncthreads();
        sstore();
        __syncthreads();
    }
    compute();
}

// ---------------- K1: qkv GEMM + fused epilogue -------------------------------
__global__ __launch_bounds__(256) void gemm_qkv_kernel(
    const float* __restrict__ A,            // [MROWS, DIMD]
    const float* __restrict__ Bm,           // [DIMD, QKVN]
    const int* __restrict__ mask)           // [MROWS]
{
    __shared__ float As[BKK][BM + PAD];
    __shared__ float Bs[BKK][BN + PAD];

    const int bm = blockIdx.y;
    const int bn = blockIdx.x;

    float acc[2][8][4];
    gemm_mainloop_tf32(A + (size_t)bm * BM * DIMD, DIMD,
                       Bm + bn * BN, QKVN, DIMD, As, Bs, acc);

    const int lane = threadIdx.x & 31;
    const int warp = threadIdx.x >> 5;
    const int wm = warp & 3;
    const int wn = warp >> 2;
    const int g = lane >> 2;
    const int tig = lane & 3;

    const int region = bn >> 3;             // 0=q 1=k 2=v (BN tile within one region)
    const int colbase = (bn & 7) * BN + wn * 64;

    #pragma unroll
    for (int im = 0; im < 2; im++) {
        const int row0 = bm * BM + wm * 32 + im * 16 + g;
        #pragma unroll
        for (int half = 0; half < 2; half++) {
            const int m = row0 + half * 8;
            const float mk = (mask[m] != 0) ? 1.0f : 0.0f;
            #pragma unroll
            for (int in = 0; in < 8; in++) {
                const int col = colbase + in * 8 + 2 * tig;
                float v0 = acc[im][in][half * 2 + 0];
                float v1 = acc[im][in][half * 2 + 1];
                float2 o;
                if (region == 0) {
                    o.x = elu1(v0); o.y = elu1(v1);
                    *(float2*)&gQ[(size_t)m * DIMD + col] = o;
                } else if (region == 1) {
                    o.x = mk * elu1(v0); o.y = mk * elu1(v1);
                    *(float2*)&gK[(size_t)m * DIMD + col] = o;
                } else {
                    o.x = mk * v0; o.y = mk * v1;
                    *(float2*)&gV[(size_t)m * DIMD + col] = o;
                }
            }
        }
    }
}

// ---------------- K2a: partial kv reduction over N chunks ---------------------
__global__ __launch_bounds__(256) void kv_reduce_kernel() {
    const int bh = blockIdx.x;               // 0..63
    const int chunk = blockIdx.y;            // 0..7
    const int b = bh / HH;
    const int h = bh % HH;
    const int tid = threadIdx.x;

    __shared__ float sk[8][64];
    __shared__ float sv[8][64];

    const int d = tid >> 2;
    const int esub = (tid & 3) * 16;

    float acc[16];
    #pragma unroll
    for (int j = 0; j < 16; j++) acc[j] = 0.0f;
    float ksacc = 0.0f;

    const size_t rowbase = (size_t)b * NN;
    const int n_lo = chunk * (NN / NCHUNK);
    const int n_hi = n_lo + (NN / NCHUNK);

    for (int n0 = n_lo; n0 < n_hi; n0 += 8) {
        #pragma unroll
        for (int r = 0; r < 4; r++) {
            const int idx = r * 256 + tid;
            const int i = idx >> 7;
            const int col = idx & 127;
            const size_t off = (rowbase + n0 + i) * DIMD + h * DHD;
            if (col < 64) sk[i][col] = gK[off + col];
            else          sv[i][col - 64] = gV[off + (col - 64)];
        }
        __syncthreads();

        #pragma unroll
        for (int i = 0; i < 8; i++) {
            const float kd = sk[i][d];
            #pragma unroll
            for (int j = 0; j < 16; j++) acc[j] += kd * sv[i][esub + j];
        }
        if (tid < 64) {
            #pragma unroll
            for (int i = 0; i < 8; i++) ksacc += sk[i][tid];
        }
        __syncthreads();
    }

    const size_t kvbase = (size_t)d * 64 + esub;
    #pragma unroll
    for (int j = 0; j < 16; j++) gKVp[chunk][bh][kvbase + j] = acc[j];
    if (tid < 64) gKsump[chunk][bh][tid] = ksacc;
}

// ---------------- K2b: finish reduction ---------------------------------------
__global__ __launch_bounds__(256) void kv_finish_kernel() {
    const int bh = blockIdx.x;
    const int tid = threadIdx.x;
    #pragma unroll
    for (int r = 0; r < 16; r++) {
        const int idx = r * 256 + tid;
        float s = 0.0f;
        #pragma unroll
        for (int c = 0; c < NCHUNK; c++) s += gKVp[c][bh][idx];
        gKV[(size_t)bh * 4096 + idx] = s;
    }
    if (tid < 64) {
        float s = 0.0f;
        #pragma unroll
        for (int c = 0; c < NCHUNK; c++) s += gKsump[c][bh][tid];
        gKsum[(size_t)bh * 64 + tid] = s;
    }
}

// ---------------- K3: out = (q @ kv) / (q . ksum + 1e-6) ----------------------
__global__ __launch_bounds__(256) void apply_kernel() {
    const int bh = blockIdx.x;
    const int chunk = blockIdx.y;
    const int b = bh / HH;
    const int h = bh % HH;
    const int tid = threadIdx.x;

    __shared__ float skv[64][64];
    __shared__ float sks[64];
    __shared__ float sq[4][64];

    {
        const size_t base = (size_t)bh * 4096;
        #pragma unroll
        for (int r = 0; r < 16; r++) {
            const int idx = r * 256 + tid;
            ((float*)skv)[idx] = gKV[base + idx];
        }
        if (tid < 64) sks[tid] = gKsum[(size_t)bh * 64 + tid];
    }
    __syncthreads();

    const int g = tid >> 6;
    const int e = tid & 63;

    for (int it = 0; it < 16; it++) {
        const int n = chunk * 64 + it * 4 + g;
        const size_t off = ((size_t)b * NN + n) * DIMD + h * DHD;
        sq[g][e] = gQ[off + e];
        __syncthreads();

        float acc = 0.0f, qd = 0.0f;
        #pragma unroll
        for (int d = 0; d < 64; d++) {
            const float qv = sq[g][d];
            acc += qv * skv[d][e];
            qd += qv * sks[d];
        }
        gS[off + e] = acc / (qd + 1e-6f);
        __syncthreads();
    }
}

// ---------------- K4: out = gS @ Wout + bout (TF32 mma) -----------------------
__global__ __launch_bounds__(256) void gemm_out_kernel(
    const float* __restrict__ Bm,
    const float* __restrict__ bout,
    float* __restrict__ Out)
{
    __shared__ float As[BKK][BM + PAD];
    __shared__ float Bs[BKK][BN + PAD];

    const int bm = blockIdx.y;
    const int bn = blockIdx.x;

    float acc[2][8][4];
    gemm_mainloop_tf32(gS + (size_t)bm * BM * DIMD, DIMD,
                       Bm + bn * BN, DIMD, DIMD, As, Bs, acc);

    const int lane = threadIdx.x & 31;
    const int warp = threadIdx.x >> 5;
    const int wm = warp & 3;
    const int wn = warp >> 2;
    const int g = lane >> 2;
    const int tig = lane & 3;

    const int colbase = bn * BN + wn * 64;

    #pragma unroll
    for (int im = 0; im < 2; im++) {
        const int row0 = bm * BM + wm * 32 + im * 16 + g;
        #pragma unroll
        for (int half = 0; half < 2; half++) {
            const int m = row0 + half * 8;
            #pragma unroll
            for (int in = 0; in < 8; in++) {
                const int col = colbase + in * 8 + 2 * tig;
                const float2 bb = *(const float2*)&bout[col];
                float2 o;
                o.x = acc[im][in][half * 2 + 0] + bb.x;
                o.y = acc[im][in][half * 2 + 1] + bb.y;
                *(float2*)&Out[(size_t)m * DIMD + col] = o;
            }
        }
    }
}

// ---------------- launcher ----------------------------------------------------
extern "C" void kernel_launch(void* const* d_in, const int* in_sizes, int n_in,
                              void* d_out, int out_size) {
    const float* x = (const float*)d_in[0];
    const int* mask = (const int*)d_in[1];
    const float* Wqkv = (const float*)d_in[2];
    const float* Wout = (const float*)d_in[3];
    const float* bout = (const float*)d_in[4];
    float* out = (float*)d_out;

    {
        dim3 grid(QKVN / BN, MROWS / BM);     // 24 x 128
        gemm_qkv_kernel<<<grid, 256>>>(x, Wqkv, mask);
    }
    {
        dim3 grid(BB * HH, NCHUNK);           // 64 x 8
        kv_reduce_kernel<<<grid, 256>>>();
    }
    {
        kv_finish_kernel<<<BB * HH, 256>>>();
    }
    {
        dim3 grid(BB * HH, NN / 64);          // 64 x 64
        apply_kernel<<<grid, 256>>>();
    }
    {
        dim3 grid(DIMD / BN, MROWS / BM);     // 8 x 128
        gemm_out_kernel<<<grid, 256>>>(Wout, bout, out);
    }
}

// round 6
// speedup vs baseline: 2.6264x; 1.0981x over previous
#include <cuda_runtime.h>
#include <cuda_bf16.h>
#include <cstdint>

// Problem constants
#define BB 4
#define NN 4096
#define DIMD 1024
#define HH 16
#define DHD 64
#define MROWS (BB * NN)          // 16384
#define QKVN (3 * DIMD)          // 3072

#define BM 128
#define BN 128
#define BKK 16
#define PAD 8
#define NCHUNK 8

// ---------------- scratch (device globals; no runtime allocation) -------------
__device__ float gQ[(size_t)MROWS * DIMD];
__device__ float gK[(size_t)MROWS * DIMD];
__device__ float gV[(size_t)MROWS * DIMD];
__device__ float gS[(size_t)MROWS * DIMD];
__device__ float gKV[(size_t)BB * HH * DHD * DHD];
__device__ float gKsum[(size_t)BB * HH * DHD];
__device__ float gKVp[NCHUNK][BB * HH][DHD * DHD];
__device__ float gKsump[NCHUNK][BB * HH][DHD];

__device__ __forceinline__ float elu1(float x) {
    return x > 0.0f ? x + 1.0f : __expf(x);
}

__device__ __forceinline__ float to_tf32(float x) {
    uint32_t r;
    asm("cvt.rna.tf32.f32 %0, %1;" : "=r"(r) : "f"(x));
    return __uint_as_float(r);
}

__device__ __forceinline__ void mma_tf32(float c[4],
                                         uint32_t a0, uint32_t a1, uint32_t a2, uint32_t a3,
                                         uint32_t b0, uint32_t b1) {
    asm volatile(
        "mma.sync.aligned.m16n8k8.row.col.f32.tf32.tf32.f32 "
        "{%0,%1,%2,%3}, {%4,%5,%6,%7}, {%8,%9}, {%0,%1,%2,%3};"
        : "+f"(c[0]), "+f"(c[1]), "+f"(c[2]), "+f"(c[3])
        : "r"(a0), "r"(a1), "r"(a2), "r"(a3), "r"(b0), "r"(b1));
}

// ---------------- shared GEMM mainloop (TF32 mma, double-buffered) ------------
__device__ __forceinline__ void gemm_mainloop_tf32(
    const float* __restrict__ Aptr, int lda,
    const float* __restrict__ Bptr, int ldb,
    int K,
    float (*As)[BKK][BM + PAD],       // [2][BKK][BM+PAD]
    float (*Bs)[BKK][BN + PAD],       // [2][BKK][BN+PAD]
    float acc[2][8][4])
{
    const int tid = threadIdx.x;
    const int lane = tid & 31;
    const int warp = tid >> 5;
    const int wm = warp & 3;
    const int wn = warp >> 2;
    const int g = lane >> 2;
    const int tig = lane & 3;

    const int a_row = tid >> 2;       // 0..63, +64 second pass
    const int a_c4 = tid & 3;
    const int b_row = tid >> 5;       // 0..7, +8 second pass
    const int b_c4 = tid & 31;

    float4 aR[2], bR[2];

    auto gload = [&](int k0) {
        #pragma unroll
        for (int p = 0; p < 2; p++) {
            aR[p] = *(const float4*)(Aptr + (size_t)(a_row + 64 * p) * lda + k0 + a_c4 * 4);
            bR[p] = *(const float4*)(Bptr + (size_t)(k0 + b_row + 8 * p) * ldb + b_c4 * 4);
        }
    };
    auto sstore = [&](int buf) {
        #pragma unroll
        for (int p = 0; p < 2; p++) {
            As[buf][a_c4 * 4 + 0][a_row + 64 * p] = to_tf32(aR[p].x);
            As[buf][a_c4 * 4 + 1][a_row + 64 * p] = to_tf32(aR[p].y);
            As[buf][a_c4 * 4 + 2][a_row + 64 * p] = to_tf32(aR[p].z);
            As[buf][a_c4 * 4 + 3][a_row + 64 * p] = to_tf32(aR[p].w);
            float4 t;
            t.x = to_tf32(bR[p].x); t.y = to_tf32(bR[p].y);
            t.z = to_tf32(bR[p].z); t.w = to_tf32(bR[p].w);
            *(float4*)&Bs[buf][b_row + 8 * p][b_c4 * 4] = t;
        }
    };
    auto compute = [&](int buf) {
        #pragma unroll
        for (int kk = 0; kk < BKK; kk += 8) {
            uint32_t af[2][4];
            #pragma unroll
            for (int im = 0; im < 2; im++) {
                const int r0 = wm * 32 + im * 16;
                af[im][0] = __float_as_uint(As[buf][kk + tig][r0 + g]);
                af[im][1] = __float_as_uint(As[buf][kk + tig][r0 + g + 8]);
                af[im][2] = __float_as_uint(As[buf][kk + tig + 4][r0 + g]);
                af[im][3] = __float_as_uint(As[buf][kk + tig + 4][r0 + g + 8]);
            }
            uint32_t bf[8][2];
            #pragma unroll
            for (int in = 0; in < 8; in++) {
                const int c0 = wn * 64 + in * 8 + g;
                bf[in][0] = __float_as_uint(Bs[buf][kk + tig][c0]);
                bf[in][1] = __float_as_uint(Bs[buf][kk + tig + 4][c0]);
            }
            #pragma unroll
            for (int im = 0; im < 2; im++)
                #pragma unroll
                for (int in = 0; in < 8; in++)
                    mma_tf32(acc[im][in],
                             af[im][0], af[im][1], af[im][2], af[im][3],
                             bf[in][0], bf[in][1]);
        }
    };

    #pragma unroll
    for (int im = 0; im < 2; im++)
        #pragma unroll
        for (int in = 0; in < 8; in++)
            #pragma unroll
            for (int j = 0; j < 4; j++) acc[im][in][j] = 0.0f;

    gload(0);
    sstore(0);
    __syncthreads();
    int cur = 0;
    for (int k0 = BKK; k0 < K; k0 += BKK) {
        gload(k0);
        compute(cur);
        sstore(cur ^ 1);
        __syncthreads();
        cur ^= 1;
    }
    compute(cur);
}

// ---------------- K1: qkv GEMM + fused epilogue -------------------------------
__global__ __launch_bounds__(256) void gemm_qkv_kernel(
    const float* __restrict__ A,
    const float* __restrict__ Bm,
    const int* __restrict__ mask)
{
    __shared__ float As[2][BKK][BM + PAD];
    __shared__ float Bs[2][BKK][BN + PAD];

    const int bm = blockIdx.y;
    const int bn = blockIdx.x;

    float acc[2][8][4];
    gemm_mainloop_tf32(A + (size_t)bm * BM * DIMD, DIMD,
                       Bm + bn * BN, QKVN, DIMD, As, Bs, acc);

    const int lane = threadIdx.x & 31;
    const int warp = threadIdx.x >> 5;
    const int wm = warp & 3;
    const int wn = warp >> 2;
    const int g = lane >> 2;
    const int tig = lane & 3;

    const int region = bn >> 3;
    const int colbase = (bn & 7) * BN + wn * 64;

    #pragma unroll
    for (int im = 0; im < 2; im++) {
        const int row0 = bm * BM + wm * 32 + im * 16 + g;
        #pragma unroll
        for (int half = 0; half < 2; half++) {
            const int m = row0 + half * 8;
            const float mk = (mask[m] != 0) ? 1.0f : 0.0f;
            #pragma unroll
            for (int in = 0; in < 8; in++) {
                const int col = colbase + in * 8 + 2 * tig;
                float v0 = acc[im][in][half * 2 + 0];
                float v1 = acc[im][in][half * 2 + 1];
                float2 o;
                if (region == 0) {
                    o.x = elu1(v0); o.y = elu1(v1);
                    *(float2*)&gQ[(size_t)m * DIMD + col] = o;
                } else if (region == 1) {
                    o.x = mk * elu1(v0); o.y = mk * elu1(v1);
                    *(float2*)&gK[(size_t)m * DIMD + col] = o;
                } else {
                    o.x = mk * v0; o.y = mk * v1;
                    *(float2*)&gV[(size_t)m * DIMD + col] = o;
                }
            }
        }
    }
}

// ---------------- K2a: partial kv reduction over N chunks ---------------------
__global__ __launch_bounds__(256) void kv_reduce_kernel() {
    const int bh = blockIdx.x;
    const int chunk = blockIdx.y;
    const int b = bh / HH;
    const int h = bh % HH;
    const int tid = threadIdx.x;

    __shared__ float sk[8][64];
    __shared__ float sv[8][64];

    const int d = tid >> 2;
    const int esub = (tid & 3) * 16;

    float acc[16];
    #pragma unroll
    for (int j = 0; j < 16; j++) acc[j] = 0.0f;
    float ksacc = 0.0f;

    const size_t rowbase = (size_t)b * NN;
    const int n_lo = chunk * (NN / NCHUNK);
    const int n_hi = n_lo + (NN / NCHUNK);

    for (int n0 = n_lo; n0 < n_hi; n0 += 8) {
        #pragma unroll
        for (int r = 0; r < 4; r++) {
            const int idx = r * 256 + tid;
            const int i = idx >> 7;
            const int col = idx & 127;
            const size_t off = (rowbase + n0 + i) * DIMD + h * DHD;
            if (col < 64) sk[i][col] = gK[off + col];
            else          sv[i][col - 64] = gV[off + (col - 64)];
        }
        __syncthreads();

        #pragma unroll
        for (int i = 0; i < 8; i++) {
            const float kd = sk[i][d];
            #pragma unroll
            for (int j = 0; j < 16; j++) acc[j] += kd * sv[i][esub + j];
        }
        if (tid < 64) {
            #pragma unroll
            for (int i = 0; i < 8; i++) ksacc += sk[i][tid];
        }
        __syncthreads();
    }

    const size_t kvbase = (size_t)d * 64 + esub;
    #pragma unroll
    for (int j = 0; j < 16; j++) gKVp[chunk][bh][kvbase + j] = acc[j];
    if (tid < 64) gKsump[chunk][bh][tid] = ksacc;
}

// ---------------- K2b: finish reduction ---------------------------------------
__global__ __launch_bounds__(256) void kv_finish_kernel() {
    const int bh = blockIdx.x;
    const int tid = threadIdx.x;
    #pragma unroll
    for (int r = 0; r < 16; r++) {
        const int idx = r * 256 + tid;
        float s = 0.0f;
        #pragma unroll
        for (int c = 0; c < NCHUNK; c++) s += gKVp[c][bh][idx];
        gKV[(size_t)bh * 4096 + idx] = s;
    }
    if (tid < 64) {
        float s = 0.0f;
        #pragma unroll
        for (int c = 0; c < NCHUNK; c++) s += gKsump[c][bh][tid];
        gKsum[(size_t)bh * 64 + tid] = s;
    }
}

// ---------------- K3: out = (q @ kv) / (q . ksum + 1e-6) ----------------------
// Block: 256 threads, 64 rows per block. Thread owns (row, 16 e's).
// One sync; register accumulation; smem = 34.3 KB (fits static 48 KB).
__global__ __launch_bounds__(256) void apply_kernel() {
    const int bh = blockIdx.x;               // 0..63
    const int chunk = blockIdx.y;            // 0..63 (64 rows each)
    const int b = bh / HH;
    const int h = bh % HH;
    const int tid = threadIdx.x;

    __shared__ float skv[64][68];
    __shared__ float sks[64];
    __shared__ float sq[64][65];

    {
        const size_t base = (size_t)bh * 4096;
        #pragma unroll
        for (int r = 0; r < 16; r++) {
            const int idx = r * 256 + tid;
            skv[idx >> 6][idx & 63] = gKV[base + idx];
        }
        if (tid < 64) sks[tid] = gKsum[(size_t)bh * 64 + tid];
    }
    const size_t qbase = ((size_t)b * NN + chunk * 64) * DIMD + h * DHD;
    {
        #pragma unroll
        for (int r = 0; r < 4; r++) {
            const int idx = r * 256 + tid;   // float4 index, 1024 total
            const int row = idx >> 4;
            const int c4 = idx & 15;
            float4 v = *(const float4*)&gQ[qbase + (size_t)row * DIMD + c4 * 4];
            sq[row][c4 * 4 + 0] = v.x;
            sq[row][c4 * 4 + 1] = v.y;
            sq[row][c4 * 4 + 2] = v.z;
            sq[row][c4 * 4 + 3] = v.w;
        }
    }
    __syncthreads();

    const int n = tid >> 2;                  // 0..63
    const int eh = (tid & 3) * 16;

    float acc[16];
    #pragma unroll
    for (int j = 0; j < 16; j++) acc[j] = 0.0f;
    float qd = 0.0f;

    #pragma unroll 4
    for (int d = 0; d < 64; d++) {
        const float qv = sq[n][d];
        qd += qv * sks[d];
        #pragma unroll
        for (int j4 = 0; j4 < 4; j4++) {
            float4 kv4 = *(const float4*)&skv[d][eh + j4 * 4];
            acc[j4 * 4 + 0] += qv * kv4.x;
            acc[j4 * 4 + 1] += qv * kv4.y;
            acc[j4 * 4 + 2] += qv * kv4.z;
            acc[j4 * 4 + 3] += qv * kv4.w;
        }
    }

    const float z = 1.0f / (qd + 1e-6f);
    float* outp = &gS[qbase + (size_t)n * DIMD + eh];
    #pragma unroll
    for (int j4 = 0; j4 < 4; j4++) {
        float4 o;
        o.x = acc[j4 * 4 + 0] * z;
        o.y = acc[j4 * 4 + 1] * z;
        o.z = acc[j4 * 4 + 2] * z;
        o.w = acc[j4 * 4 + 3] * z;
        *(float4*)(outp + j4 * 4) = o;
    }
}

// ---------------- K4: out = gS @ Wout + bout (TF32 mma) -----------------------
__global__ __launch_bounds__(256) void gemm_out_kernel(
    const float* __restrict__ Bm,
    const float* __restrict__ bout,
    float* __restrict__ Out)
{
    __shared__ float As[2][BKK][BM + PAD];
    __shared__ float Bs[2][BKK][BN + PAD];

    const int bm = blockIdx.y;
    const int bn = blockIdx.x;

    float acc[2][8][4];
    gemm_mainloop_tf32(gS + (size_t)bm * BM * DIMD, DIMD,
                       Bm + bn * BN, DIMD, DIMD, As, Bs, acc);

    const int lane = threadIdx.x & 31;
    const int warp = threadIdx.x >> 5;
    const int wm = warp & 3;
    const int wn = warp >> 2;
    const int g = lane >> 2;
    const int tig = lane & 3;

    const int colbase = bn * BN + wn * 64;

    #pragma unroll
    for (int im = 0; im < 2; im++) {
        const int row0 = bm * BM + wm * 32 + im * 16 + g;
        #pragma unroll
        for (int half = 0; half < 2; half++) {
            const int m = row0 + half * 8;
            #pragma unroll
            for (int in = 0; in < 8; in++) {
                const int col = colbase + in * 8 + 2 * tig;
                const float2 bb = *(const float2*)&bout[col];
                float2 o;
                o.x = acc[im][in][half * 2 + 0] + bb.x;
                o.y = acc[im][in][half * 2 + 1] + bb.y;
                *(float2*)&Out[(size_t)m * DIMD + col] = o;
            }
        }
    }
}

// ---------------- launcher ----------------------------------------------------
extern "C" void kernel_launch(void* const* d_in, const int* in_sizes, int n_in,
                              void* d_out, int out_size) {
    const float* x = (const float*)d_in[0];
    const int* mask = (const int*)d_in[1];
    const float* Wqkv = (const float*)d_in[2];
    const float* Wout = (const float*)d_in[3];
    const float* bout = (const float*)d_in[4];
    float* out = (float*)d_out;

    {
        dim3 grid(QKVN / BN, MROWS / BM);     // 24 x 128
        gemm_qkv_kernel<<<grid, 256>>>(x, Wqkv, mask);
    }
    {
        dim3 grid(BB * HH, NCHUNK);           // 64 x 8
        kv_reduce_kernel<<<grid, 256>>>();
    }
    {
        kv_finish_kernel<<<BB * HH, 256>>>();
    }
    {
        dim3 grid(BB * HH, NN / 64);          // 64 x 64
        apply_kernel<<<grid, 256>>>();
    }
    {
        dim3 grid(DIMD / BN, MROWS / BM);     // 8 x 128
        gemm_out_kernel<<<grid, 256>>>(Wout, bout, out);
    }
}

// round 7
// speedup vs baseline: 2.7859x; 1.0607x over previous
#include <cuda_runtime.h>
#include <cuda_bf16.h>
#include <cstdint>

// Problem constants
#define BB 4
#define NN 4096
#define DIMD 1024
#define HH 16
#define DHD 64
#define MROWS (BB * NN)          // 16384
#define QKVN (3 * DIMD)          // 3072

#define BM 128
#define BN 128
#define BKK 16
#define STAGES 4
#define APADK 4                   // A smem k-stride = 16+4 = 20
#define BPAD 8                    // B smem n-stride = 136
#define NCHUNK 8

#define A_STRIDE (BKK + APADK)    // 20
#define B_STRIDE (BN + BPAD)      // 136
#define A_STAGE_FLOATS (BM * A_STRIDE)        // 2560
#define B_STAGE_FLOATS (BKK * B_STRIDE)       // 2176
#define GEMM_SMEM_BYTES (STAGES * (A_STAGE_FLOATS + B_STAGE_FLOATS) * 4)  // 75776

// ---------------- scratch (device globals; no runtime allocation) -------------
__device__ float gQ[(size_t)MROWS * DIMD];
__device__ float gK[(size_t)MROWS * DIMD];
__device__ float gV[(size_t)MROWS * DIMD];
__device__ float gS[(size_t)MROWS * DIMD];
__device__ float gKV[(size_t)BB * HH * DHD * DHD];
__device__ float gKsum[(size_t)BB * HH * DHD];
__device__ float gKVp[NCHUNK][BB * HH][DHD * DHD];
__device__ float gKsump[NCHUNK][BB * HH][DHD];

__device__ __forceinline__ float elu1(float x) {
    return x > 0.0f ? x + 1.0f : __expf(x);
}

__device__ __forceinline__ uint32_t tf32_bits(float x) {
    uint32_t r;
    asm("cvt.rna.tf32.f32 %0, %1;" : "=r"(r) : "f"(x));
    return r;
}

__device__ __forceinline__ void mma_tf32(float c[4],
                                         uint32_t a0, uint32_t a1, uint32_t a2, uint32_t a3,
                                         uint32_t b0, uint32_t b1) {
    asm volatile(
        "mma.sync.aligned.m16n8k8.row.col.f32.tf32.tf32.f32 "
        "{%0,%1,%2,%3}, {%4,%5,%6,%7}, {%8,%9}, {%0,%1,%2,%3};"
        : "+f"(c[0]), "+f"(c[1]), "+f"(c[2]), "+f"(c[3])
        : "r"(a0), "r"(a1), "r"(a2), "r"(a3), "r"(b0), "r"(b1));
}

__device__ __forceinline__ void cp_async16(uint32_t saddr, const void* gptr) {
    asm volatile("cp.async.cg.shared.global [%0], [%1], 16;" :: "r"(saddr), "l"(gptr));
}
__device__ __forceinline__ void cp_commit() {
    asm volatile("cp.async.commit_group;");
}
__device__ __forceinline__ void cp_wait2() {
    asm volatile("cp.async.wait_group 2;");
}

// ---------------- GEMM mainloop: 4-stage cp.async, TF32 mma -------------------
// A in smem [m][k] (stride 20), B in smem [k][n] (stride 136). cvt after LDS.
__device__ __forceinline__ void gemm_mainloop_tf32(
    const float* __restrict__ Aptr, int lda,     // &A[bm*128][0]
    const float* __restrict__ Bptr, int ldb,     // &B[0][bn*128]
    int K,
    float acc[2][8][4])
{
    extern __shared__ float dynsmem[];
    float* Asm = dynsmem;                                    // [STAGES][BM][A_STRIDE]
    float* Bsm = dynsmem + STAGES * A_STAGE_FLOATS;          // [STAGES][BKK][B_STRIDE]
    const uint32_t As_base = (uint32_t)__cvta_generic_to_shared(Asm);
    const uint32_t Bs_base = (uint32_t)__cvta_generic_to_shared(Bsm);

    const int tid = threadIdx.x;
    const int lane = tid & 31;
    const int warp = tid >> 5;
    const int wm = warp & 3;
    const int wn = warp >> 2;
    const int g = lane >> 2;
    const int tig = lane & 3;

    const int NK = K / BKK;

    auto prefetch = [&](int ks) {
        const int s = ks & (STAGES - 1);
        const int k0 = ks * BKK;
        #pragma unroll
        for (int i = 0; i < 2; i++) {
            const int c = tid * 2 + i;            // 0..511
            // A chunk: row = c>>2, kc = (c&3)*4
            {
                const int row = c >> 2;
                const int kc = (c & 3) * 4;
                const float* gp = Aptr + (size_t)row * lda + k0 + kc;
                uint32_t sa = As_base + (uint32_t)(((s * BM + row) * A_STRIDE + kc) * 4);
                cp_async16(sa, gp);
            }
            // B chunk: bk = c>>5, nc = (c&31)*4
            {
                const int bk = c >> 5;
                const int nc = (c & 31) * 4;
                const float* gp = Bptr + (size_t)(k0 + bk) * ldb + nc;
                uint32_t sb = Bs_base + (uint32_t)(((s * BKK + bk) * B_STRIDE + nc) * 4);
                cp_async16(sb, gp);
            }
        }
        cp_commit();
    };

    auto compute = [&](int s) {
        const float* Astage = Asm + s * A_STAGE_FLOATS;
        const float* Bstage = Bsm + s * B_STAGE_FLOATS;
        #pragma unroll
        for (int kk = 0; kk < BKK; kk += 8) {
            uint32_t af[2][4];
            #pragma unroll
            for (int im = 0; im < 2; im++) {
                const int r0 = wm * 32 + im * 16;
                af[im][0] = tf32_bits(Astage[(r0 + g) * A_STRIDE + kk + tig]);
                af[im][1] = tf32_bits(Astage[(r0 + g + 8) * A_STRIDE + kk + tig]);
                af[im][2] = tf32_bits(Astage[(r0 + g) * A_STRIDE + kk + tig + 4]);
                af[im][3] = tf32_bits(Astage[(r0 + g + 8) * A_STRIDE + kk + tig + 4]);
            }
            uint32_t bf[8][2];
            #pragma unroll
            for (int in = 0; in < 8; in++) {
                const int c0 = wn * 64 + in * 8 + g;
                bf[in][0] = tf32_bits(Bstage[(kk + tig) * B_STRIDE + c0]);
                bf[in][1] = tf32_bits(Bstage[(kk + tig + 4) * B_STRIDE + c0]);
            }
            #pragma unroll
            for (int im = 0; im < 2; im++)
                #pragma unroll
                for (int in = 0; in < 8; in++)
                    mma_tf32(acc[im][in],
                             af[im][0], af[im][1], af[im][2], af[im][3],
                             bf[in][0], bf[in][1]);
        }
    };

    #pragma unroll
    for (int im = 0; im < 2; im++)
        #pragma unroll
        for (int in = 0; in < 8; in++)
            #pragma unroll
            for (int j = 0; j < 4; j++) acc[im][in][j] = 0.0f;

    prefetch(0);
    prefetch(1);
    prefetch(2);
    for (int ks = 0; ks < NK; ks++) {
        cp_wait2();                  // stage ks data resident (this thread's groups)
        __syncthreads();             // all threads' chunks visible; prev compute done
        compute(ks & (STAGES - 1));
        if (ks + 3 < NK) prefetch(ks + 3);
        else cp_commit();            // keep group accounting uniform
    }
}

// ---------------- K1: qkv GEMM + fused epilogue -------------------------------
__global__ __launch_bounds__(256) void gemm_qkv_kernel(
    const float* __restrict__ A,
    const float* __restrict__ Bm,
    const int* __restrict__ mask)
{
    const int bm = blockIdx.y;
    const int bn = blockIdx.x;

    float acc[2][8][4];
    gemm_mainloop_tf32(A + (size_t)bm * BM * DIMD, DIMD,
                       Bm + bn * BN, QKVN, DIMD, acc);

    const int lane = threadIdx.x & 31;
    const int warp = threadIdx.x >> 5;
    const int wm = warp & 3;
    const int wn = warp >> 2;
    const int g = lane >> 2;
    const int tig = lane & 3;

    const int region = bn >> 3;
    const int colbase = (bn & 7) * BN + wn * 64;

    #pragma unroll
    for (int im = 0; im < 2; im++) {
        const int row0 = bm * BM + wm * 32 + im * 16 + g;
        #pragma unroll
        for (int half = 0; half < 2; half++) {
            const int m = row0 + half * 8;
            const float mk = (mask[m] != 0) ? 1.0f : 0.0f;
            #pragma unroll
            for (int in = 0; in < 8; in++) {
                const int col = colbase + in * 8 + 2 * tig;
                float v0 = acc[im][in][half * 2 + 0];
                float v1 = acc[im][in][half * 2 + 1];
                float2 o;
                if (region == 0) {
                    o.x = elu1(v0); o.y = elu1(v1);
                    *(float2*)&gQ[(size_t)m * DIMD + col] = o;
                } else if (region == 1) {
                    o.x = mk * elu1(v0); o.y = mk * elu1(v1);
                    *(float2*)&gK[(size_t)m * DIMD + col] = o;
                } else {
                    o.x = mk * v0; o.y = mk * v1;
                    *(float2*)&gV[(size_t)m * DIMD + col] = o;
                }
            }
        }
    }
}

// ---------------- K2a: partial kv reduction over N chunks ---------------------
__global__ __launch_bounds__(256) void kv_reduce_kernel() {
    const int bh = blockIdx.x;
    const int chunk = blockIdx.y;
    const int b = bh / HH;
    const int h = bh % HH;
    const int tid = threadIdx.x;

    __shared__ float sk[8][64];
    __shared__ float sv[8][64];

    const int d = tid >> 2;
    const int esub = (tid & 3) * 16;

    float acc[16];
    #pragma unroll
    for (int j = 0; j < 16; j++) acc[j] = 0.0f;
    float ksacc = 0.0f;

    const size_t rowbase = (size_t)b * NN;
    const int n_lo = chunk * (NN / NCHUNK);
    const int n_hi = n_lo + (NN / NCHUNK);

    for (int n0 = n_lo; n0 < n_hi; n0 += 8) {
        #pragma unroll
        for (int r = 0; r < 4; r++) {
            const int idx = r * 256 + tid;
            const int i = idx >> 7;
            const int col = idx & 127;
            const size_t off = (rowbase + n0 + i) * DIMD + h * DHD;
            if (col < 64) sk[i][col] = gK[off + col];
            else          sv[i][col - 64] = gV[off + (col - 64)];
        }
        __syncthreads();

        #pragma unroll
        for (int i = 0; i < 8; i++) {
            const float kd = sk[i][d];
            #pragma unroll
            for (int j4 = 0; j4 < 4; j4++) {
                float4 v4 = *(const float4*)&sv[i][esub + j4 * 4];
                acc[j4 * 4 + 0] += kd * v4.x;
                acc[j4 * 4 + 1] += kd * v4.y;
                acc[j4 * 4 + 2] += kd * v4.z;
                acc[j4 * 4 + 3] += kd * v4.w;
            }
        }
        if (tid < 64) {
            #pragma unroll
            for (int i = 0; i < 8; i++) ksacc += sk[i][tid];
        }
        __syncthreads();
    }

    const size_t kvbase = (size_t)d * 64 + esub;
    #pragma unroll
    for (int j = 0; j < 16; j++) gKVp[chunk][bh][kvbase + j] = acc[j];
    if (tid < 64) gKsump[chunk][bh][tid] = ksacc;
}

// ---------------- K2b: finish reduction ---------------------------------------
__global__ __launch_bounds__(256) void kv_finish_kernel() {
    const int bh = blockIdx.x;
    const int tid = threadIdx.x;
    #pragma unroll
    for (int r = 0; r < 16; r++) {
        const int idx = r * 256 + tid;
        float s = 0.0f;
        #pragma unroll
        for (int c = 0; c < NCHUNK; c++) s += gKVp[c][bh][idx];
        gKV[(size_t)bh * 4096 + idx] = s;
    }
    if (tid < 64) {
        float s = 0.0f;
        #pragma unroll
        for (int c = 0; c < NCHUNK; c++) s += gKsump[c][bh][tid];
        gKsum[(size_t)bh * 64 + tid] = s;
    }
}

// ---------------- K3: out = (q @ kv) / (q . ksum + 1e-6) ----------------------
// 256 threads, 256 rows/block. Thread owns 4 rows x 16 e. q from global (L1),
// kv in smem, skv float4 loads amortized over 4 rows.
__global__ __launch_bounds__(256) void apply_kernel() {
    const int bh = blockIdx.x;               // 0..63
    const int chunk = blockIdx.y;            // 0..15 (256 rows each)
    const int b = bh / HH;
    const int h = bh % HH;
    const int tid = threadIdx.x;

    __shared__ float skv[64][68];
    __shared__ float sks[64];

    {
        const size_t base = (size_t)bh * 4096;
        #pragma unroll
        for (int r = 0; r < 4; r++) {
            const int f4 = r * 256 + tid;        // 0..1023
            const int row = f4 >> 4;
            const int c4 = f4 & 15;
            float4 v = *(const float4*)&gKV[base + (size_t)f4 * 4];
            skv[row][c4 * 4 + 0] = v.x;
            skv[row][c4 * 4 + 1] = v.y;
            skv[row][c4 * 4 + 2] = v.z;
            skv[row][c4 * 4 + 3] = v.w;
        }
        if (tid < 64) sks[tid] = gKsum[(size_t)bh * 64 + tid];
    }
    __syncthreads();

    const int rg = tid >> 2;                 // 0..63
    const int eh = (tid & 3) * 16;
    const int n0 = chunk * 256 + rg * 4;
    const size_t qbase = ((size_t)b * NN + n0) * DIMD + h * DHD;

    float acc[4][16];
    float qd[4];
    #pragma unroll
    for (int r = 0; r < 4; r++) {
        qd[r] = 0.0f;
        #pragma unroll
        for (int j = 0; j < 16; j++) acc[r][j] = 0.0f;
    }

    for (int d4 = 0; d4 < 16; d4++) {
        float4 qv[4];
        #pragma unroll
        for (int r = 0; r < 4; r++)
            qv[r] = *(const float4*)&gQ[qbase + (size_t)r * DIMD + d4 * 4];

        #pragma unroll
        for (int dd = 0; dd < 4; dd++) {
            const int d = d4 * 4 + dd;
            float4 kv0 = *(const float4*)&skv[d][eh + 0];
            float4 kv1 = *(const float4*)&skv[d][eh + 4];
            float4 kv2 = *(const float4*)&skv[d][eh + 8];
            float4 kv3 = *(const float4*)&skv[d][eh + 12];
            const float ks = sks[d];
            #pragma unroll
            for (int r = 0; r < 4; r++) {
                const float* qp = (const float*)&qv[r];
                const float q = qp[dd];
                qd[r] += q * ks;
                acc[r][0]  += q * kv0.x; acc[r][1]  += q * kv0.y;
                acc[r][2]  += q * kv0.z; acc[r][3]  += q * kv0.w;
                acc[r][4]  += q * kv1.x; acc[r][5]  += q * kv1.y;
                acc[r][6]  += q * kv1.z; acc[r][7]  += q * kv1.w;
                acc[r][8]  += q * kv2.x; acc[r][9]  += q * kv2.y;
                acc[r][10] += q * kv2.z; acc[r][11] += q * kv2.w;
                acc[r][12] += q * kv3.x; acc[r][13] += q * kv3.y;
                acc[r][14] += q * kv3.z; acc[r][15] += q * kv3.w;
            }
        }
    }

    #pragma unroll
    for (int r = 0; r < 4; r++) {
        const float z = 1.0f / (qd[r] + 1e-6f);
        float* outp = &gS[qbase + (size_t)r * DIMD + eh];
        #pragma unroll
        for (int j4 = 0; j4 < 4; j4++) {
            float4 o;
            o.x = acc[r][j4 * 4 + 0] * z;
            o.y = acc[r][j4 * 4 + 1] * z;
            o.z = acc[r][j4 * 4 + 2] * z;
            o.w = acc[r][j4 * 4 + 3] * z;
            *(float4*)(outp + j4 * 4) = o;
        }
    }
}

// ---------------- K4: out = gS @ Wout + bout (TF32 mma) -----------------------
__global__ __launch_bounds__(256) void gemm_out_kernel(
    const float* __restrict__ Bm,
    const float* __restrict__ bout,
    float* __restrict__ Out)
{
    const int bm = blockIdx.y;
    const int bn = blockIdx.x;

    float acc[2][8][4];
    gemm_mainloop_tf32(gS + (size_t)bm * BM * DIMD, DIMD,
                       Bm + bn * BN, DIMD, DIMD, acc);

    const int lane = threadIdx.x & 31;
    const int warp = threadIdx.x >> 5;
    const int wm = warp & 3;
    const int wn = warp >> 2;
    const int g = lane >> 2;
    const int tig = lane & 3;

    const int colbase = bn * BN + wn * 64;

    #pragma unroll
    for (int im = 0; im < 2; im++) {
        const int row0 = bm * BM + wm * 32 + im * 16 + g;
        #pragma unroll
        for (int half = 0; half < 2; half++) {
            const int m = row0 + half * 8;
            #pragma unroll
            for (int in = 0; in < 8; in++) {
                const int col = colbase + in * 8 + 2 * tig;
                const float2 bb = *(const float2*)&bout[col];
                float2 o;
                o.x = acc[im][in][half * 2 + 0] + bb.x;
                o.y = acc[im][in][half * 2 + 1] + bb.y;
                *(float2*)&Out[(size_t)m * DIMD + col] = o;
            }
        }
    }
}

// ---------------- launcher ----------------------------------------------------
extern "C" void kernel_launch(void* const* d_in, const int* in_sizes, int n_in,
                              void* d_out, int out_size) {
    const float* x = (const float*)d_in[0];
    const int* mask = (const int*)d_in[1];
    const float* Wqkv = (const float*)d_in[2];
    const float* Wout = (const float*)d_in[3];
    const float* bout = (const float*)d_in[4];
    float* out = (float*)d_out;

    cudaFuncSetAttribute(gemm_qkv_kernel,
                         cudaFuncAttributeMaxDynamicSharedMemorySize, GEMM_SMEM_BYTES);
    cudaFuncSetAttribute(gemm_out_kernel,
                         cudaFuncAttributeMaxDynamicSharedMemorySize, GEMM_SMEM_BYTES);

    {
        dim3 grid(QKVN / BN, MROWS / BM);     // 24 x 128
        gemm_qkv_kernel<<<grid, 256, GEMM_SMEM_BYTES>>>(x, Wqkv, mask);
    }
    {
        dim3 grid(BB * HH, NCHUNK);           // 64 x 8
        kv_reduce_kernel<<<grid, 256>>>();
    }
    {
        kv_finish_kernel<<<BB * HH, 256>>>();
    }
    {
        dim3 grid(BB * HH, NN / 256);         // 64 x 16
        apply_kernel<<<grid, 256>>>();
    }
    {
        dim3 grid(DIMD / BN, MROWS / BM);     // 8 x 128
        gemm_out_kernel<<<grid, 256, GEMM_SMEM_BYTES>>>(Wout, bout, out);
    }
}